// round 3
// baseline (speedup 1.0000x reference)
#include <cuda_runtime.h>
#include <cuda_bf16.h>
#include <math_constants.h>

// Problem constants
#define NPIX 2304          // 48*48
#define CIN  256
#define HID  128           // heads*dim_head
#define NHEADS 4
#define DHEAD 32
#define BATCH 8
#define QSCALE 0.17677669529663687f   // 1/sqrt(32)

// Scratch (allocation-free rule: __device__ globals)
__device__ float g_q[BATCH * HID * NPIX];   // [bh][d][n], q pre-scaled
__device__ float g_k[BATCH * HID * NPIX];   // [bh][d][n]
__device__ float g_v[BATCH * HID * NPIX];   // [bh][d][n]
__device__ float g_o[BATCH * HID * NPIX];   // [b][c][n], c = h*32+d

// ---------------------------------------------------------------------------
// Kernel 1: QKV projection.  C[384, 2304] = W[384,256] @ X_b[256,2304]
// Tiled GEMM BM=64 BN=64 BK=16, 256 threads, 4x4 per thread.
// Routes outputs into g_q (scaled), g_k, g_v in [bh][d][n] layout.
// ---------------------------------------------------------------------------
__global__ void qkv_kernel(const float* __restrict__ x,
                           const float* __restrict__ w)
{
    __shared__ float As[16][64];   // As[k][o]
    __shared__ float Bs[16][64];   // Bs[k][n]

    const int b  = blockIdx.z;
    const int ob = blockIdx.y * 64;
    const int nb = blockIdx.x * 64;
    const int tid = threadIdx.x;

    const float* xb = x + (size_t)b * CIN * NPIX;

    float acc[4][4] = {};
    const int to = (tid >> 4) << 2;   // 0..60
    const int tn = (tid & 15) << 2;   // 0..60

    for (int kb = 0; kb < CIN; kb += 16) {
        #pragma unroll
        for (int i = tid; i < 64 * 16; i += 256) {
            int o = i >> 4, k = i & 15;
            As[k][o] = w[(ob + o) * CIN + kb + k];
        }
        #pragma unroll
        for (int i = tid; i < 16 * 64; i += 256) {
            int k = i >> 6, n = i & 63;
            Bs[k][n] = xb[(size_t)(kb + k) * NPIX + nb + n];
        }
        __syncthreads();
        #pragma unroll
        for (int k = 0; k < 16; k++) {
            float4 a = *(const float4*)&As[k][to];
            float4 bb = *(const float4*)&Bs[k][tn];
            float av[4] = {a.x, a.y, a.z, a.w};
            float bv[4] = {bb.x, bb.y, bb.z, bb.w};
            #pragma unroll
            for (int i = 0; i < 4; i++)
                #pragma unroll
                for (int j = 0; j < 4; j++)
                    acc[i][j] = fmaf(av[i], bv[j], acc[i][j]);
        }
        __syncthreads();
    }

    #pragma unroll
    for (int i = 0; i < 4; i++) {
        int o   = ob + to + i;
        int sec = o >> 7;           // 0=q,1=k,2=v
        int oc  = o & 127;
        int bh  = b * NHEADS + (oc >> 5);
        int d   = oc & 31;
        float mult = (sec == 0) ? QSCALE : 1.0f;
        float4 val = make_float4(acc[i][0] * mult, acc[i][1] * mult,
                                 acc[i][2] * mult, acc[i][3] * mult);
        float* dst = (sec == 0) ? g_q : (sec == 1) ? g_k : g_v;
        *(float4*)&dst[((size_t)(bh * 32 + d)) * NPIX + nb + tn] = val;
    }
}

// ---------------------------------------------------------------------------
// Kernel 2: flash attention. One thread = one query. 128 queries/block.
// K/V tiles (32 keys x 32 dims) staged in smem, broadcast float4 reads.
// Online softmax fully per-thread (no cross-thread reductions needed).
// ---------------------------------------------------------------------------
__global__ void __launch_bounds__(128) attn_kernel()
{
    const int bh = blockIdx.y;
    const int qn = blockIdx.x * 128 + threadIdx.x;

    const float* qp = g_q + (size_t)bh * DHEAD * NPIX;
    const float* kp = g_k + (size_t)bh * DHEAD * NPIX;
    const float* vp = g_v + (size_t)bh * DHEAD * NPIX;

    float q[32];
    #pragma unroll
    for (int d = 0; d < 32; d++)
        q[d] = qp[(size_t)d * NPIX + qn];       // coalesced per d

    float acc[32] = {};
    float m = -CUDART_INF_F;
    float l = 0.0f;

    __shared__ float ks[32 * 32];   // [d][j] as float4-friendly flat array
    __shared__ float vs[32 * 32];

    for (int kb = 0; kb < NPIX; kb += 32) {
        __syncthreads();
        #pragma unroll
        for (int i = threadIdx.x; i < 32 * 8; i += 128) {  // 256 float4 per array
            int d = i >> 3, j4 = i & 7;
            const size_t src = (size_t)d * NPIX + kb + j4 * 4;
            ((float4*)ks)[i] = *(const float4*)&kp[src];
            ((float4*)vs)[i] = *(const float4*)&vp[src];
        }
        __syncthreads();

        float s[32];
        #pragma unroll
        for (int j4 = 0; j4 < 8; j4++) {
            float4 a4 = make_float4(0.f, 0.f, 0.f, 0.f);
            #pragma unroll
            for (int d = 0; d < 32; d++) {
                float4 kk = ((const float4*)ks)[d * 8 + j4];   // broadcast
                a4.x = fmaf(q[d], kk.x, a4.x);
                a4.y = fmaf(q[d], kk.y, a4.y);
                a4.z = fmaf(q[d], kk.z, a4.z);
                a4.w = fmaf(q[d], kk.w, a4.w);
            }
            s[4 * j4 + 0] = a4.x; s[4 * j4 + 1] = a4.y;
            s[4 * j4 + 2] = a4.z; s[4 * j4 + 3] = a4.w;
        }

        float mt = s[0];
        #pragma unroll
        for (int j = 1; j < 32; j++) mt = fmaxf(mt, s[j]);
        float mnew = fmaxf(m, mt);
        float alpha = __expf(m - mnew);          // first iter: exp(-inf)=0
        l *= alpha;
        #pragma unroll
        for (int d = 0; d < 32; d++) acc[d] *= alpha;
        #pragma unroll
        for (int j = 0; j < 32; j++) {
            s[j] = __expf(s[j] - mnew);
            l += s[j];
        }
        #pragma unroll
        for (int d = 0; d < 32; d++) {
            float a = acc[d];
            #pragma unroll
            for (int j4 = 0; j4 < 8; j4++) {
                float4 vv = ((const float4*)vs)[d * 8 + j4];   // broadcast
                a = fmaf(s[4 * j4 + 0], vv.x, a);
                a = fmaf(s[4 * j4 + 1], vv.y, a);
                a = fmaf(s[4 * j4 + 2], vv.z, a);
                a = fmaf(s[4 * j4 + 3], vv.w, a);
            }
            acc[d] = a;
        }
        m = mnew;
    }

    const float inv = 1.0f / l;
    float* op = g_o + (size_t)bh * DHEAD * NPIX;   // bh*32+d == b*128 + h*32+d
    #pragma unroll
    for (int d = 0; d < 32; d++)
        op[(size_t)d * NPIX + qn] = acc[d] * inv;   // coalesced per d
}

// ---------------------------------------------------------------------------
// Kernel 3: output projection + bias.
// C[256, 2304] = W_out[256,128] @ G_o[b][128, 2304] + b_out
// ---------------------------------------------------------------------------
__global__ void proj_kernel(const float* __restrict__ w,
                            const float* __restrict__ bias,
                            float* __restrict__ out)
{
    __shared__ float As[16][64];
    __shared__ float Bs[16][64];

    const int b  = blockIdx.z;
    const int ob = blockIdx.y * 64;
    const int nb = blockIdx.x * 64;
    const int tid = threadIdx.x;

    const float* gb = g_o + (size_t)b * HID * NPIX;

    float acc[4][4] = {};
    const int to = (tid >> 4) << 2;
    const int tn = (tid & 15) << 2;

    for (int kb = 0; kb < HID; kb += 16) {
        #pragma unroll
        for (int i = tid; i < 64 * 16; i += 256) {
            int o = i >> 4, k = i & 15;
            As[k][o] = w[(ob + o) * HID + kb + k];
        }
        #pragma unroll
        for (int i = tid; i < 16 * 64; i += 256) {
            int k = i >> 6, n = i & 63;
            Bs[k][n] = gb[(size_t)(kb + k) * NPIX + nb + n];
        }
        __syncthreads();
        #pragma unroll
        for (int k = 0; k < 16; k++) {
            float4 a = *(const float4*)&As[k][to];
            float4 bb = *(const float4*)&Bs[k][tn];
            float av[4] = {a.x, a.y, a.z, a.w};
            float bv[4] = {bb.x, bb.y, bb.z, bb.w};
            #pragma unroll
            for (int i = 0; i < 4; i++)
                #pragma unroll
                for (int j = 0; j < 4; j++)
                    acc[i][j] = fmaf(av[i], bv[j], acc[i][j]);
        }
        __syncthreads();
    }

    #pragma unroll
    for (int i = 0; i < 4; i++) {
        int o = ob + to + i;
        float bv = bias[o];
        float4 val = make_float4(acc[i][0] + bv, acc[i][1] + bv,
                                 acc[i][2] + bv, acc[i][3] + bv);
        *(float4*)&out[((size_t)(b * CIN + o)) * NPIX + nb + tn] = val;
    }
}

// ---------------------------------------------------------------------------
extern "C" void kernel_launch(void* const* d_in, const int* in_sizes, int n_in,
                              void* d_out, int out_size)
{
    const float* x     = (const float*)d_in[0];  // [8,256,48,48]
    const float* w_qkv = (const float*)d_in[1];  // [384,256]
    const float* w_out = (const float*)d_in[2];  // [256,128]
    const float* b_out = (const float*)d_in[3];  // [256]
    float* out = (float*)d_out;                  // [8,256,48,48]

    // Kernel 1: QKV projection
    {
        dim3 grid(NPIX / 64, (3 * HID) / 64, BATCH);   // 36 x 6 x 8
        qkv_kernel<<<grid, 256>>>(x, w_qkv);
    }
    // Kernel 2: attention
    {
        dim3 grid(NPIX / 128, BATCH * NHEADS);          // 18 x 32
        attn_kernel<<<grid, 128>>>();
    }
    // Kernel 3: output projection
    {
        dim3 grid(NPIX / 64, CIN / 64, BATCH);          // 36 x 4 x 8
        proj_kernel<<<grid, 256>>>(w_out, b_out, out);
    }
}

// round 12
// speedup vs baseline: 1.5439x; 1.5439x over previous
#include <cuda_runtime.h>
#include <cuda_bf16.h>
#include <math_constants.h>

// Problem constants
#define NPIX 2304          // 48*48
#define CIN  256
#define HID  128           // heads*dim_head
#define NHEADS 4
#define DHEAD 32
#define BATCH 8
#define QSCALE 0.17677669529663687f   // 1/sqrt(32)

// Scratch (allocation-free rule: __device__ globals)
__device__ float g_q[BATCH * HID * NPIX];   // [bh][d][n], q pre-scaled
__device__ float g_k[BATCH * HID * NPIX];   // [bh][d][n]
__device__ float g_v[BATCH * HID * NPIX];   // [bh][d][n]
__device__ float g_o[BATCH * HID * NPIX];   // [b][c][n], c = h*32+d

// ---------------------------------------------------------------------------
// Kernel 1: QKV projection.  C[384, 2304] = W[384,256] @ X_b[256,2304]
// ---------------------------------------------------------------------------
__global__ void qkv_kernel(const float* __restrict__ x,
                           const float* __restrict__ w)
{
    __shared__ float As[16][64];   // As[k][o]
    __shared__ float Bs[16][64];   // Bs[k][n]

    const int b  = blockIdx.z;
    const int ob = blockIdx.y * 64;
    const int nb = blockIdx.x * 64;
    const int tid = threadIdx.x;

    const float* xb = x + (size_t)b * CIN * NPIX;

    float acc[4][4] = {};
    const int to = (tid >> 4) << 2;   // 0..60
    const int tn = (tid & 15) << 2;   // 0..60

    for (int kb = 0; kb < CIN; kb += 16) {
        #pragma unroll
        for (int i = tid; i < 64 * 16; i += 256) {
            int o = i >> 4, k = i & 15;
            As[k][o] = w[(ob + o) * CIN + kb + k];
        }
        #pragma unroll
        for (int i = tid; i < 16 * 64; i += 256) {
            int k = i >> 6, n = i & 63;
            Bs[k][n] = xb[(size_t)(kb + k) * NPIX + nb + n];
        }
        __syncthreads();
        #pragma unroll
        for (int k = 0; k < 16; k++) {
            float4 a = *(const float4*)&As[k][to];
            float4 bb = *(const float4*)&Bs[k][tn];
            float av[4] = {a.x, a.y, a.z, a.w};
            float bv[4] = {bb.x, bb.y, bb.z, bb.w};
            #pragma unroll
            for (int i = 0; i < 4; i++)
                #pragma unroll
                for (int j = 0; j < 4; j++)
                    acc[i][j] = fmaf(av[i], bv[j], acc[i][j]);
        }
        __syncthreads();
    }

    #pragma unroll
    for (int i = 0; i < 4; i++) {
        int o   = ob + to + i;
        int sec = o >> 7;           // 0=q,1=k,2=v
        int oc  = o & 127;
        int bh  = b * NHEADS + (oc >> 5);
        int d   = oc & 31;
        float mult = (sec == 0) ? QSCALE : 1.0f;
        float4 val = make_float4(acc[i][0] * mult, acc[i][1] * mult,
                                 acc[i][2] * mult, acc[i][3] * mult);
        float* dst = (sec == 0) ? g_q : (sec == 1) ? g_k : g_v;
        *(float4*)&dst[((size_t)(bh * 32 + d)) * NPIX + nb + tn] = val;
    }
}

// ---------------------------------------------------------------------------
// Kernel 2: flash attention on mma.sync m16n8k8 with 3xTF32 error
// compensation (a*b ~= ah*bh + ah*bl + al*bh -> ~fp32 accuracy).
// Block = 64 queries (4 warps x 16). Loop over 36 key-tiles of 64.
// ---------------------------------------------------------------------------
#define KTILE 64
#define QTILE 64
#define SST   68    // smem row stride (floats); 68*4B = 272B = 17*16B (f4-aligned)

__device__ __forceinline__ void mma_tf32(float d[4], const unsigned a[4],
                                         unsigned b0, unsigned b1)
{
    asm volatile(
        "mma.sync.aligned.m16n8k8.row.col.f32.tf32.tf32.f32 "
        "{%0,%1,%2,%3}, {%4,%5,%6,%7}, {%8,%9}, {%0,%1,%2,%3};\n"
        : "+f"(d[0]), "+f"(d[1]), "+f"(d[2]), "+f"(d[3])
        : "r"(a[0]), "r"(a[1]), "r"(a[2]), "r"(a[3]), "r"(b0), "r"(b1));
}

// Split fp32 -> (tf32 hi, tf32 lo) with v ~= hi + lo
__device__ __forceinline__ void split_tf32(float v, unsigned& hi, unsigned& lo)
{
    unsigned h;
    asm("cvt.rna.tf32.f32 %0, %1;" : "=r"(h) : "f"(v));
    float lf = v - __uint_as_float(h);
    unsigned l;
    asm("cvt.rna.tf32.f32 %0, %1;" : "=r"(l) : "f"(lf));
    hi = h; lo = l;
}

__device__ __forceinline__ float rmax4(float v) {
    v = fmaxf(v, __shfl_xor_sync(0xffffffffu, v, 1));
    v = fmaxf(v, __shfl_xor_sync(0xffffffffu, v, 2));
    return v;
}
__device__ __forceinline__ float rsum4(float v) {
    v += __shfl_xor_sync(0xffffffffu, v, 1);
    v += __shfl_xor_sync(0xffffffffu, v, 2);
    return v;
}

__global__ void __launch_bounds__(128) attn_mma_kernel()
{
    __shared__ float Ks[32 * SST];        // K^T tile: [dim][key]  (fp32)
    __shared__ float Vs[32 * SST];        // V^T tile: [dim][key]  (fp32)
    __shared__ float Ps[4 * 16 * SST];    // per-warp P staging [row][key]

    const int bh    = blockIdx.y;
    const int qbase = blockIdx.x * QTILE;
    const int tid   = threadIdx.x;
    const int warp  = tid >> 5;
    const int lane  = tid & 31;
    const int g     = lane >> 2;   // row group
    const int t     = lane & 3;    // thread-in-group

    const float* qp = g_q + (size_t)bh * DHEAD * NPIX;
    const float* kp = g_k + (size_t)bh * DHEAD * NPIX;
    const float* vp = g_v + (size_t)bh * DHEAD * NPIX;

    // Resident Q fragments, split hi/lo: 4 k-frags (dim chunks of 8) x 4 regs
    unsigned qh[4][4], ql[4][4];
    const int qA = qbase + warp * 16 + g;
    const int qB = qA + 8;
    #pragma unroll
    for (int kf = 0; kf < 4; kf++) {
        int d0 = kf * 8 + t, d1 = d0 + 4;
        split_tf32(qp[(size_t)d0 * NPIX + qA], qh[kf][0], ql[kf][0]);
        split_tf32(qp[(size_t)d0 * NPIX + qB], qh[kf][1], ql[kf][1]);
        split_tf32(qp[(size_t)d1 * NPIX + qA], qh[kf][2], ql[kf][2]);
        split_tf32(qp[(size_t)d1 * NPIX + qB], qh[kf][3], ql[kf][3]);
    }

    float o[4][4] = {};
    float mA = -CUDART_INF_F, mB = -CUDART_INF_F;
    float lA = 0.f, lB = 0.f;
    float* Pw = Ps + warp * 16 * SST;

    for (int kb = 0; kb < NPIX; kb += KTILE) {
        __syncthreads();
        #pragma unroll
        for (int i = tid; i < 32 * 16; i += 128) {   // 512 float4 per array
            int d = i >> 4, j4 = i & 15;
            *(float4*)&Ks[d * SST + j4 * 4] =
                *(const float4*)&kp[(size_t)d * NPIX + kb + j4 * 4];
            *(float4*)&Vs[d * SST + j4 * 4] =
                *(const float4*)&vp[(size_t)d * NPIX + kb + j4 * 4];
        }
        __syncthreads();

        // ---- S = Q K^T  (16 x 64 per warp), 3xTF32 ----
        float s[8][4];
        #pragma unroll
        for (int nt = 0; nt < 8; nt++)
            s[nt][0] = s[nt][1] = s[nt][2] = s[nt][3] = 0.f;
        #pragma unroll
        for (int kf = 0; kf < 4; kf++) {
            #pragma unroll
            for (int nt = 0; nt < 8; nt++) {
                float b0f = Ks[(kf * 8 + t)     * SST + nt * 8 + g];
                float b1f = Ks[(kf * 8 + t + 4) * SST + nt * 8 + g];
                unsigned b0h, b0l, b1h, b1l;
                split_tf32(b0f, b0h, b0l);
                split_tf32(b1f, b1h, b1l);
                mma_tf32(s[nt], qh[kf], b0h, b1h);
                mma_tf32(s[nt], qh[kf], b0l, b1l);
                mma_tf32(s[nt], ql[kf], b0h, b1h);
            }
        }

        // ---- online softmax (rows qA = g, qB = g+8) ----
        float tA = -CUDART_INF_F, tB = -CUDART_INF_F;
        #pragma unroll
        for (int nt = 0; nt < 8; nt++) {
            tA = fmaxf(tA, fmaxf(s[nt][0], s[nt][1]));
            tB = fmaxf(tB, fmaxf(s[nt][2], s[nt][3]));
        }
        tA = rmax4(tA); tB = rmax4(tB);
        float mAn = fmaxf(mA, tA), mBn = fmaxf(mB, tB);
        float aA = __expf(mA - mAn), aB = __expf(mB - mBn);

        float sumA = 0.f, sumB = 0.f;
        #pragma unroll
        for (int nt = 0; nt < 8; nt++) {
            float p0 = __expf(s[nt][0] - mAn);
            float p1 = __expf(s[nt][1] - mAn);
            float p2 = __expf(s[nt][2] - mBn);
            float p3 = __expf(s[nt][3] - mBn);
            sumA += p0 + p1; sumB += p2 + p3;
            *(float2*)&Pw[g       * SST + nt * 8 + 2 * t] = make_float2(p0, p1);
            *(float2*)&Pw[(g + 8) * SST + nt * 8 + 2 * t] = make_float2(p2, p3);
        }
        sumA = rsum4(sumA); sumB = rsum4(sumB);
        lA = lA * aA + sumA;
        lB = lB * aB + sumB;
        mA = mAn; mB = mBn;
        #pragma unroll
        for (int nt = 0; nt < 4; nt++) {
            o[nt][0] *= aA; o[nt][1] *= aA;
            o[nt][2] *= aB; o[nt][3] *= aB;
        }
        __syncwarp();

        // ---- O += P V  (16 x 32 per warp, k = 64 keys), 3xTF32 ----
        #pragma unroll
        for (int kf = 0; kf < 8; kf++) {
            unsigned pah[4], pal[4];
            split_tf32(Pw[g       * SST + kf * 8 + t],     pah[0], pal[0]);
            split_tf32(Pw[(g + 8) * SST + kf * 8 + t],     pah[1], pal[1]);
            split_tf32(Pw[g       * SST + kf * 8 + t + 4], pah[2], pal[2]);
            split_tf32(Pw[(g + 8) * SST + kf * 8 + t + 4], pah[3], pal[3]);
            #pragma unroll
            for (int nt = 0; nt < 4; nt++) {
                float b0f = Vs[(nt * 8 + g) * SST + kf * 8 + t];
                float b1f = Vs[(nt * 8 + g) * SST + kf * 8 + t + 4];
                unsigned b0h, b0l, b1h, b1l;
                split_tf32(b0f, b0h, b0l);
                split_tf32(b1f, b1h, b1l);
                mma_tf32(o[nt], pah, b0h, b1h);
                mma_tf32(o[nt], pah, b0l, b1l);
                mma_tf32(o[nt], pal, b0h, b1h);
            }
        }
    }

    // ---- epilogue: normalize + store to g_o [d][n] ----
    const float iA = 1.0f / lA, iB = 1.0f / lB;
    float* op = g_o + (size_t)bh * DHEAD * NPIX;
    #pragma unroll
    for (int nt = 0; nt < 4; nt++) {
        int d0 = nt * 8 + 2 * t, d1 = d0 + 1;
        op[(size_t)d0 * NPIX + qA] = o[nt][0] * iA;
        op[(size_t)d1 * NPIX + qA] = o[nt][1] * iA;
        op[(size_t)d0 * NPIX + qB] = o[nt][2] * iB;
        op[(size_t)d1 * NPIX + qB] = o[nt][3] * iB;
    }
}

// ---------------------------------------------------------------------------
// Kernel 3: output projection + bias.
// ---------------------------------------------------------------------------
__global__ void proj_kernel(const float* __restrict__ w,
                            const float* __restrict__ bias,
                            float* __restrict__ out)
{
    __shared__ float As[16][64];
    __shared__ float Bs[16][64];

    const int b  = blockIdx.z;
    const int ob = blockIdx.y * 64;
    const int nb = blockIdx.x * 64;
    const int tid = threadIdx.x;

    const float* gb = g_o + (size_t)b * HID * NPIX;

    float acc[4][4] = {};
    const int to = (tid >> 4) << 2;
    const int tn = (tid & 15) << 2;

    for (int kb = 0; kb < HID; kb += 16) {
        #pragma unroll
        for (int i = tid; i < 64 * 16; i += 256) {
            int o = i >> 4, k = i & 15;
            As[k][o] = w[(ob + o) * HID + kb + k];
        }
        #pragma unroll
        for (int i = tid; i < 16 * 64; i += 256) {
            int k = i >> 6, n = i & 63;
            Bs[k][n] = gb[(size_t)(kb + k) * NPIX + nb + n];
        }
        __syncthreads();
        #pragma unroll
        for (int k = 0; k < 16; k++) {
            float4 a = *(const float4*)&As[k][to];
            float4 bb = *(const float4*)&Bs[k][tn];
            float av[4] = {a.x, a.y, a.z, a.w};
            float bv[4] = {bb.x, bb.y, bb.z, bb.w};
            #pragma unroll
            for (int i = 0; i < 4; i++)
                #pragma unroll
                for (int j = 0; j < 4; j++)
                    acc[i][j] = fmaf(av[i], bv[j], acc[i][j]);
        }
        __syncthreads();
    }

    #pragma unroll
    for (int i = 0; i < 4; i++) {
        int o = ob + to + i;
        float bv = bias[o];
        float4 val = make_float4(acc[i][0] + bv, acc[i][1] + bv,
                                 acc[i][2] + bv, acc[i][3] + bv);
        *(float4*)&out[((size_t)(b * CIN + o)) * NPIX + nb + tn] = val;
    }
}

// ---------------------------------------------------------------------------
extern "C" void kernel_launch(void* const* d_in, const int* in_sizes, int n_in,
                              void* d_out, int out_size)
{
    const float* x     = (const float*)d_in[0];  // [8,256,48,48]
    const float* w_qkv = (const float*)d_in[1];  // [384,256]
    const float* w_out = (const float*)d_in[2];  // [256,128]
    const float* b_out = (const float*)d_in[3];  // [256]
    float* out = (float*)d_out;                  // [8,256,48,48]

    {
        dim3 grid(NPIX / 64, (3 * HID) / 64, BATCH);   // 36 x 6 x 8
        qkv_kernel<<<grid, 256>>>(x, w_qkv);
    }
    {
        dim3 grid(NPIX / QTILE, BATCH * NHEADS);        // 36 x 32
        attn_mma_kernel<<<grid, 128>>>();
    }
    {
        dim3 grid(NPIX / 64, CIN / 64, BATCH);          // 36 x 4 x 8
        proj_kernel<<<grid, 256>>>(w_out, b_out, out);
    }
}

// round 13
// speedup vs baseline: 1.7934x; 1.1616x over previous
#include <cuda_runtime.h>
#include <cuda_bf16.h>
#include <math_constants.h>

// Problem constants
#define NPIX 2304          // 48*48
#define CIN  256
#define HID  128           // heads*dim_head
#define NHEADS 4
#define DHEAD 32
#define BATCH 8
#define QSCALE 0.17677669529663687f   // 1/sqrt(32)

// Scratch (allocation-free rule: __device__ globals)
__device__ float g_q[BATCH * HID * NPIX];   // [bh][d][n], q pre-scaled
__device__ float g_k[BATCH * HID * NPIX];   // [bh][d][n]
__device__ float g_v[BATCH * HID * NPIX];   // [bh][d][n]
__device__ float g_o[BATCH * HID * NPIX];   // [b][c][n], c = h*32+d

// ---------------------------------------------------------------------------
// Shared helpers: m16n8k8 TF32 mma + fp32 -> (tf32 hi, tf32 lo) split
// ---------------------------------------------------------------------------
__device__ __forceinline__ void mma_tf32(float d[4], const unsigned a[4],
                                         unsigned b0, unsigned b1)
{
    asm volatile(
        "mma.sync.aligned.m16n8k8.row.col.f32.tf32.tf32.f32 "
        "{%0,%1,%2,%3}, {%4,%5,%6,%7}, {%8,%9}, {%0,%1,%2,%3};\n"
        : "+f"(d[0]), "+f"(d[1]), "+f"(d[2]), "+f"(d[3])
        : "r"(a[0]), "r"(a[1]), "r"(a[2]), "r"(a[3]), "r"(b0), "r"(b1));
}

__device__ __forceinline__ void split_tf32(float v, unsigned& hi, unsigned& lo)
{
    unsigned h;
    asm("cvt.rna.tf32.f32 %0, %1;" : "=r"(h) : "f"(v));
    float lf = v - __uint_as_float(h);
    unsigned l;
    asm("cvt.rna.tf32.f32 %0, %1;" : "=r"(l) : "f"(lf));
    hi = h; lo = l;
}

__device__ __forceinline__ float rmax4(float v) {
    v = fmaxf(v, __shfl_xor_sync(0xffffffffu, v, 1));
    v = fmaxf(v, __shfl_xor_sync(0xffffffffu, v, 2));
    return v;
}
__device__ __forceinline__ float rsum4(float v) {
    v += __shfl_xor_sync(0xffffffffu, v, 1);
    v += __shfl_xor_sync(0xffffffffu, v, 2);
    return v;
}

#define GST 68   // GEMM smem row stride (uints); 68*4B f4/u4-aligned

// ---------------------------------------------------------------------------
// Kernel 1: QKV projection on 3xTF32 mma.
// C[384, 2304] = W[384,256] @ X_b[256,2304]; 64x64 tile, 4 warps.
// Epilogue routes to g_q (scaled) / g_k / g_v in [bh][d][n] layout.
// ---------------------------------------------------------------------------
__global__ void __launch_bounds__(128) qkv_mma_kernel(const float* __restrict__ x,
                                                      const float* __restrict__ w)
{
    __shared__ __align__(16) unsigned Wh[32 * GST], Wl[32 * GST];   // [k][o]
    __shared__ __align__(16) unsigned Xh[32 * GST], Xl[32 * GST];   // [k][n]

    const int b  = blockIdx.z;
    const int ob = blockIdx.y * 64;
    const int nb = blockIdx.x * 64;
    const int tid  = threadIdx.x;
    const int warp = tid >> 5;
    const int lane = tid & 31;
    const int g = lane >> 2, t = lane & 3;
    const int wo = warp * 16;

    const float* xb = x + (size_t)b * CIN * NPIX;

    float acc[8][4] = {};

    for (int kb = 0; kb < CIN; kb += 32) {
        __syncthreads();
        // W tile: 64o x 32k -> [k][o] split hi/lo
        #pragma unroll
        for (int j = 0; j < 4; j++) {
            int idx = tid + j * 128;
            int o = idx >> 3, k4 = (idx & 7) * 4;
            float4 wv = *(const float4*)&w[(ob + o) * CIN + kb + k4];
            unsigned h, l;
            split_tf32(wv.x, h, l); Wh[(k4 + 0) * GST + o] = h; Wl[(k4 + 0) * GST + o] = l;
            split_tf32(wv.y, h, l); Wh[(k4 + 1) * GST + o] = h; Wl[(k4 + 1) * GST + o] = l;
            split_tf32(wv.z, h, l); Wh[(k4 + 2) * GST + o] = h; Wl[(k4 + 2) * GST + o] = l;
            split_tf32(wv.w, h, l); Wh[(k4 + 3) * GST + o] = h; Wl[(k4 + 3) * GST + o] = l;
        }
        // X tile: 32k x 64n -> [k][n] split hi/lo
        #pragma unroll
        for (int j = 0; j < 4; j++) {
            int idx = tid + j * 128;
            int k = idx >> 4, n4 = (idx & 15) * 4;
            float4 xv = *(const float4*)&xb[(size_t)(kb + k) * NPIX + nb + n4];
            unsigned h0, l0, h1, l1, h2, l2, h3, l3;
            split_tf32(xv.x, h0, l0); split_tf32(xv.y, h1, l1);
            split_tf32(xv.z, h2, l2); split_tf32(xv.w, h3, l3);
            *(uint4*)&Xh[k * GST + n4] = make_uint4(h0, h1, h2, h3);
            *(uint4*)&Xl[k * GST + n4] = make_uint4(l0, l1, l2, l3);
        }
        __syncthreads();

        #pragma unroll
        for (int kf = 0; kf < 4; kf++) {
            const int r0 = kf * 8 + t, r1 = r0 + 4;
            unsigned ah[4], al[4];
            ah[0] = Wh[r0 * GST + wo + g];     al[0] = Wl[r0 * GST + wo + g];
            ah[1] = Wh[r0 * GST + wo + g + 8]; al[1] = Wl[r0 * GST + wo + g + 8];
            ah[2] = Wh[r1 * GST + wo + g];     al[2] = Wl[r1 * GST + wo + g];
            ah[3] = Wh[r1 * GST + wo + g + 8]; al[3] = Wl[r1 * GST + wo + g + 8];
            #pragma unroll
            for (int nt = 0; nt < 8; nt++) {
                unsigned b0h = Xh[r0 * GST + nt * 8 + g];
                unsigned b1h = Xh[r1 * GST + nt * 8 + g];
                unsigned b0l = Xl[r0 * GST + nt * 8 + g];
                unsigned b1l = Xl[r1 * GST + nt * 8 + g];
                mma_tf32(acc[nt], ah, b0h, b1h);
                mma_tf32(acc[nt], ah, b0l, b1l);
                mma_tf32(acc[nt], al, b0h, b1h);
            }
        }
    }

    // Epilogue: rows oA (acc[.][0,1]) and oB (acc[.][2,3]); cols nb+nt*8+2t(+1)
    #pragma unroll
    for (int r = 0; r < 2; r++) {
        int o   = ob + wo + g + r * 8;
        int sec = o >> 7;            // 0=q,1=k,2=v (uniform per block)
        int oc  = o & 127;
        int bh  = b * NHEADS + (oc >> 5);
        int d   = oc & 31;
        float mult = (sec == 0) ? QSCALE : 1.0f;
        float* dst = (sec == 0) ? g_q : (sec == 1) ? g_k : g_v;
        float* row = dst + (size_t)(bh * 32 + d) * NPIX + nb + 2 * t;
        #pragma unroll
        for (int nt = 0; nt < 8; nt++)
            *(float2*)&row[nt * 8] = make_float2(acc[nt][2 * r] * mult,
                                                 acc[nt][2 * r + 1] * mult);
    }
}

// ---------------------------------------------------------------------------
// Kernel 2: flash attention on 3xTF32 mma; K/V split once at tile-load time.
// Ps staging aliases the (dead-after-S) K hi/lo region to stay < 48KB.
// ---------------------------------------------------------------------------
#define KTILE 64
#define QTILE 64
#define SST   68

__global__ void __launch_bounds__(128) attn_mma_kernel()
{
    __shared__ __align__(16) unsigned sbuf[4 * 32 * SST];
    unsigned* Ksh = sbuf;                    // [dim][key] hi
    unsigned* Ksl = sbuf + 32 * SST;         // [dim][key] lo
    float*    Ps  = (float*)sbuf;            // aliases K region (4 warps x 16 x SST)
    unsigned* Vsh = sbuf + 2 * 32 * SST;
    unsigned* Vsl = sbuf + 3 * 32 * SST;

    const int bh    = blockIdx.y;
    const int qbase = blockIdx.x * QTILE;
    const int tid   = threadIdx.x;
    const int warp  = tid >> 5;
    const int lane  = tid & 31;
    const int g     = lane >> 2;
    const int t     = lane & 3;

    const float* qp = g_q + (size_t)bh * DHEAD * NPIX;
    const float* kp = g_k + (size_t)bh * DHEAD * NPIX;
    const float* vp = g_v + (size_t)bh * DHEAD * NPIX;

    // Resident Q fragments (hi/lo)
    unsigned qh[4][4], ql[4][4];
    const int qA = qbase + warp * 16 + g;
    const int qB = qA + 8;
    #pragma unroll
    for (int kf = 0; kf < 4; kf++) {
        int d0 = kf * 8 + t, d1 = d0 + 4;
        split_tf32(qp[(size_t)d0 * NPIX + qA], qh[kf][0], ql[kf][0]);
        split_tf32(qp[(size_t)d0 * NPIX + qB], qh[kf][1], ql[kf][1]);
        split_tf32(qp[(size_t)d1 * NPIX + qA], qh[kf][2], ql[kf][2]);
        split_tf32(qp[(size_t)d1 * NPIX + qB], qh[kf][3], ql[kf][3]);
    }

    float o[4][4] = {};
    float mA = -CUDART_INF_F, mB = -CUDART_INF_F;
    float lA = 0.f, lB = 0.f;
    float* Pw = Ps + warp * 16 * SST;

    for (int kb = 0; kb < NPIX; kb += KTILE) {
        __syncthreads();   // all PV reads of Ps/Vs done before overwrite
        #pragma unroll
        for (int i = tid; i < 32 * 16; i += 128) {
            int d = i >> 4, j4 = (i & 15) * 4;
            float4 kv = *(const float4*)&kp[(size_t)d * NPIX + kb + j4];
            float4 vv = *(const float4*)&vp[(size_t)d * NPIX + kb + j4];
            unsigned h0, l0, h1, l1, h2, l2, h3, l3;
            split_tf32(kv.x, h0, l0); split_tf32(kv.y, h1, l1);
            split_tf32(kv.z, h2, l2); split_tf32(kv.w, h3, l3);
            *(uint4*)&Ksh[d * SST + j4] = make_uint4(h0, h1, h2, h3);
            *(uint4*)&Ksl[d * SST + j4] = make_uint4(l0, l1, l2, l3);
            split_tf32(vv.x, h0, l0); split_tf32(vv.y, h1, l1);
            split_tf32(vv.z, h2, l2); split_tf32(vv.w, h3, l3);
            *(uint4*)&Vsh[d * SST + j4] = make_uint4(h0, h1, h2, h3);
            *(uint4*)&Vsl[d * SST + j4] = make_uint4(l0, l1, l2, l3);
        }
        __syncthreads();

        // ---- S = Q K^T  (16 x 64 per warp), 3xTF32 ----
        float s[8][4];
        #pragma unroll
        for (int nt = 0; nt < 8; nt++)
            s[nt][0] = s[nt][1] = s[nt][2] = s[nt][3] = 0.f;
        #pragma unroll
        for (int kf = 0; kf < 4; kf++) {
            const int r0 = kf * 8 + t, r1 = r0 + 4;
            #pragma unroll
            for (int nt = 0; nt < 8; nt++) {
                unsigned b0h = Ksh[r0 * SST + nt * 8 + g];
                unsigned b1h = Ksh[r1 * SST + nt * 8 + g];
                unsigned b0l = Ksl[r0 * SST + nt * 8 + g];
                unsigned b1l = Ksl[r1 * SST + nt * 8 + g];
                mma_tf32(s[nt], qh[kf], b0h, b1h);
                mma_tf32(s[nt], qh[kf], b0l, b1l);
                mma_tf32(s[nt], ql[kf], b0h, b1h);
            }
        }

        // ---- online softmax (rows qA = g, qB = g+8); p computed in-place ----
        float tA = -CUDART_INF_F, tB = -CUDART_INF_F;
        #pragma unroll
        for (int nt = 0; nt < 8; nt++) {
            tA = fmaxf(tA, fmaxf(s[nt][0], s[nt][1]));
            tB = fmaxf(tB, fmaxf(s[nt][2], s[nt][3]));
        }
        tA = rmax4(tA); tB = rmax4(tB);
        float mAn = fmaxf(mA, tA), mBn = fmaxf(mB, tB);
        float aA = __expf(mA - mAn), aB = __expf(mB - mBn);

        float sumA = 0.f, sumB = 0.f;
        #pragma unroll
        for (int nt = 0; nt < 8; nt++) {
            s[nt][0] = __expf(s[nt][0] - mAn);
            s[nt][1] = __expf(s[nt][1] - mAn);
            s[nt][2] = __expf(s[nt][2] - mBn);
            s[nt][3] = __expf(s[nt][3] - mBn);
            sumA += s[nt][0] + s[nt][1];
            sumB += s[nt][2] + s[nt][3];
        }
        sumA = rsum4(sumA); sumB = rsum4(sumB);
        lA = lA * aA + sumA;
        lB = lB * aB + sumB;
        mA = mAn; mB = mBn;
        #pragma unroll
        for (int nt = 0; nt < 4; nt++) {
            o[nt][0] *= aA; o[nt][1] *= aA;
            o[nt][2] *= aB; o[nt][3] *= aB;
        }

        __syncthreads();   // all S-phase reads of Ks done before Ps overwrite

        #pragma unroll
        for (int nt = 0; nt < 8; nt++) {
            *(float2*)&Pw[g       * SST + nt * 8 + 2 * t] = make_float2(s[nt][0], s[nt][1]);
            *(float2*)&Pw[(g + 8) * SST + nt * 8 + 2 * t] = make_float2(s[nt][2], s[nt][3]);
        }
        __syncwarp();

        // ---- O += P V  (16 x 32 per warp, k = 64 keys), 3xTF32 ----
        #pragma unroll
        for (int kf = 0; kf < 8; kf++) {
            unsigned pah[4], pal[4];
            split_tf32(Pw[g       * SST + kf * 8 + t],     pah[0], pal[0]);
            split_tf32(Pw[(g + 8) * SST + kf * 8 + t],     pah[1], pal[1]);
            split_tf32(Pw[g       * SST + kf * 8 + t + 4], pah[2], pal[2]);
            split_tf32(Pw[(g + 8) * SST + kf * 8 + t + 4], pah[3], pal[3]);
            #pragma unroll
            for (int nt = 0; nt < 4; nt++) {
                unsigned b0h = Vsh[(nt * 8 + g) * SST + kf * 8 + t];
                unsigned b1h = Vsh[(nt * 8 + g) * SST + kf * 8 + t + 4];
                unsigned b0l = Vsl[(nt * 8 + g) * SST + kf * 8 + t];
                unsigned b1l = Vsl[(nt * 8 + g) * SST + kf * 8 + t + 4];
                mma_tf32(o[nt], pah, b0h, b1h);
                mma_tf32(o[nt], pah, b0l, b1l);
                mma_tf32(o[nt], pal, b0h, b1h);
            }
        }
    }

    // ---- epilogue: normalize + store to g_o [d][n] ----
    const float iA = 1.0f / lA, iB = 1.0f / lB;
    float* op = g_o + (size_t)bh * DHEAD * NPIX;
    #pragma unroll
    for (int nt = 0; nt < 4; nt++) {
        int d0 = nt * 8 + 2 * t, d1 = d0 + 1;
        op[(size_t)d0 * NPIX + qA] = o[nt][0] * iA;
        op[(size_t)d1 * NPIX + qA] = o[nt][1] * iA;
        op[(size_t)d0 * NPIX + qB] = o[nt][2] * iB;
        op[(size_t)d1 * NPIX + qB] = o[nt][3] * iB;
    }
}

// ---------------------------------------------------------------------------
// Kernel 3: output projection on 3xTF32 mma + bias.
// C[256, 2304] = W_out[256,128] @ G_o[b][128,2304] + b_out
// ---------------------------------------------------------------------------
__global__ void __launch_bounds__(128) proj_mma_kernel(const float* __restrict__ w,
                                                       const float* __restrict__ bias,
                                                       float* __restrict__ out)
{
    __shared__ __align__(16) unsigned Wh[32 * GST], Wl[32 * GST];   // [k][o]
    __shared__ __align__(16) unsigned Xh[32 * GST], Xl[32 * GST];   // [k][n]

    const int b  = blockIdx.z;
    const int ob = blockIdx.y * 64;
    const int nb = blockIdx.x * 64;
    const int tid  = threadIdx.x;
    const int warp = tid >> 5;
    const int lane = tid & 31;
    const int g = lane >> 2, t = lane & 3;
    const int wo = warp * 16;

    const float* gb = g_o + (size_t)b * HID * NPIX;

    float acc[8][4] = {};

    for (int kb = 0; kb < HID; kb += 32) {
        __syncthreads();
        #pragma unroll
        for (int j = 0; j < 4; j++) {
            int idx = tid + j * 128;
            int o = idx >> 3, k4 = (idx & 7) * 4;
            float4 wv = *(const float4*)&w[(ob + o) * HID + kb + k4];
            unsigned h, l;
            split_tf32(wv.x, h, l); Wh[(k4 + 0) * GST + o] = h; Wl[(k4 + 0) * GST + o] = l;
            split_tf32(wv.y, h, l); Wh[(k4 + 1) * GST + o] = h; Wl[(k4 + 1) * GST + o] = l;
            split_tf32(wv.z, h, l); Wh[(k4 + 2) * GST + o] = h; Wl[(k4 + 2) * GST + o] = l;
            split_tf32(wv.w, h, l); Wh[(k4 + 3) * GST + o] = h; Wl[(k4 + 3) * GST + o] = l;
        }
        #pragma unroll
        for (int j = 0; j < 4; j++) {
            int idx = tid + j * 128;
            int k = idx >> 4, n4 = (idx & 15) * 4;
            float4 xv = *(const float4*)&gb[(size_t)(kb + k) * NPIX + nb + n4];
            unsigned h0, l0, h1, l1, h2, l2, h3, l3;
            split_tf32(xv.x, h0, l0); split_tf32(xv.y, h1, l1);
            split_tf32(xv.z, h2, l2); split_tf32(xv.w, h3, l3);
            *(uint4*)&Xh[k * GST + n4] = make_uint4(h0, h1, h2, h3);
            *(uint4*)&Xl[k * GST + n4] = make_uint4(l0, l1, l2, l3);
        }
        __syncthreads();

        #pragma unroll
        for (int kf = 0; kf < 4; kf++) {
            const int r0 = kf * 8 + t, r1 = r0 + 4;
            unsigned ah[4], al[4];
            ah[0] = Wh[r0 * GST + wo + g];     al[0] = Wl[r0 * GST + wo + g];
            ah[1] = Wh[r0 * GST + wo + g + 8]; al[1] = Wl[r0 * GST + wo + g + 8];
            ah[2] = Wh[r1 * GST + wo + g];     al[2] = Wl[r1 * GST + wo + g];
            ah[3] = Wh[r1 * GST + wo + g + 8]; al[3] = Wl[r1 * GST + wo + g + 8];
            #pragma unroll
            for (int nt = 0; nt < 8; nt++) {
                unsigned b0h = Xh[r0 * GST + nt * 8 + g];
                unsigned b1h = Xh[r1 * GST + nt * 8 + g];
                unsigned b0l = Xl[r0 * GST + nt * 8 + g];
                unsigned b1l = Xl[r1 * GST + nt * 8 + g];
                mma_tf32(acc[nt], ah, b0h, b1h);
                mma_tf32(acc[nt], ah, b0l, b1l);
                mma_tf32(acc[nt], al, b0h, b1h);
            }
        }
    }

    #pragma unroll
    for (int r = 0; r < 2; r++) {
        int o = ob + wo + g + r * 8;
        float bv = bias[o];
        float* row = out + (size_t)(b * CIN + o) * NPIX + nb + 2 * t;
        #pragma unroll
        for (int nt = 0; nt < 8; nt++)
            *(float2*)&row[nt * 8] = make_float2(acc[nt][2 * r] + bv,
                                                 acc[nt][2 * r + 1] + bv);
    }
}

// ---------------------------------------------------------------------------
extern "C" void kernel_launch(void* const* d_in, const int* in_sizes, int n_in,
                              void* d_out, int out_size)
{
    const float* x     = (const float*)d_in[0];  // [8,256,48,48]
    const float* w_qkv = (const float*)d_in[1];  // [384,256]
    const float* w_out = (const float*)d_in[2];  // [256,128]
    const float* b_out = (const float*)d_in[3];  // [256]
    float* out = (float*)d_out;                  // [8,256,48,48]

    {
        dim3 grid(NPIX / 64, (3 * HID) / 64, BATCH);   // 36 x 6 x 8
        qkv_mma_kernel<<<grid, 128>>>(x, w_qkv);
    }
    {
        dim3 grid(NPIX / QTILE, BATCH * NHEADS);        // 36 x 32
        attn_mma_kernel<<<grid, 128>>>();
    }
    {
        dim3 grid(NPIX / 64, CIN / 64, BATCH);          // 36 x 4 x 8
        proj_mma_kernel<<<grid, 128>>>(w_out, b_out, out);
    }
}

// round 14
// speedup vs baseline: 2.1235x; 1.1841x over previous
#include <cuda_runtime.h>
#include <cuda_bf16.h>
#include <math_constants.h>

// Problem constants
#define NPIX 2304          // 48*48
#define CIN  256
#define HID  128           // heads*dim_head
#define NHEADS 4
#define DHEAD 32
#define BATCH 8
#define QSCALE 0.17677669529663687f   // 1/sqrt(32)

// Scratch (allocation-free rule: __device__ globals)
__device__ float g_q[BATCH * HID * NPIX];   // [bh][d][n], q pre-scaled
__device__ float g_k[BATCH * HID * NPIX];   // [bh][d][n]
__device__ float g_v[BATCH * HID * NPIX];   // [bh][d][n]
__device__ float g_o[BATCH * HID * NPIX];   // [b][c][n], c = h*32+d

// ---------------------------------------------------------------------------
// Shared helpers
// ---------------------------------------------------------------------------
__device__ __forceinline__ void mma_tf32(float d[4], const unsigned a[4],
                                         unsigned b0, unsigned b1)
{
    asm volatile(
        "mma.sync.aligned.m16n8k8.row.col.f32.tf32.tf32.f32 "
        "{%0,%1,%2,%3}, {%4,%5,%6,%7}, {%8,%9}, {%0,%1,%2,%3};\n"
        : "+f"(d[0]), "+f"(d[1]), "+f"(d[2]), "+f"(d[3])
        : "r"(a[0]), "r"(a[1]), "r"(a[2]), "r"(a[3]), "r"(b0), "r"(b1));
}

__device__ __forceinline__ void split_tf32(float v, unsigned& hi, unsigned& lo)
{
    unsigned h;
    asm("cvt.rna.tf32.f32 %0, %1;" : "=r"(h) : "f"(v));
    float lf = v - __uint_as_float(h);
    unsigned l;
    asm("cvt.rna.tf32.f32 %0, %1;" : "=r"(l) : "f"(lf));
    hi = h; lo = l;
}

__device__ __forceinline__ float rmax4(float v) {
    v = fmaxf(v, __shfl_xor_sync(0xffffffffu, v, 1));
    v = fmaxf(v, __shfl_xor_sync(0xffffffffu, v, 2));
    return v;
}
__device__ __forceinline__ float rsum4(float v) {
    v += __shfl_xor_sync(0xffffffffu, v, 1);
    v += __shfl_xor_sync(0xffffffffu, v, 2);
    return v;
}

// ---------------------------------------------------------------------------
// Kernel 1: QKV projection on 3xTF32 mma.  M-tile 128 (warp = 32 rows, 2
// m-frags per B-load), N-tile 64, k-step 16.
// ---------------------------------------------------------------------------
#define WST 136   // W smem stride: banks 8t+g -> conflict-free A loads
#define XST 72    // X smem stride: banks 8t+g -> conflict-free B loads

__global__ void __launch_bounds__(128) qkv_mma_kernel(const float* __restrict__ x,
                                                      const float* __restrict__ w)
{
    __shared__ __align__(16) unsigned Wh[16 * WST], Wl[16 * WST];   // [k][o]
    __shared__ __align__(16) unsigned Xh[16 * XST], Xl[16 * XST];   // [k][n]

    const int b  = blockIdx.z;
    const int ob = blockIdx.y * 128;
    const int nb = blockIdx.x * 64;
    const int tid  = threadIdx.x;
    const int warp = tid >> 5;
    const int lane = tid & 31;
    const int g = lane >> 2, t = lane & 3;

    const float* xb = x + (size_t)b * CIN * NPIX;

    float acc[2][8][4] = {};

    for (int kb = 0; kb < CIN; kb += 16) {
        __syncthreads();
        // W tile: 128o x 16k -> [k][o] hi/lo
        #pragma unroll
        for (int j = 0; j < 4; j++) {
            int idx = tid + j * 128;
            int o = idx >> 2, k4 = (idx & 3) * 4;
            float4 wv = *(const float4*)&w[(ob + o) * CIN + kb + k4];
            unsigned h, l;
            split_tf32(wv.x, h, l); Wh[(k4 + 0) * WST + o] = h; Wl[(k4 + 0) * WST + o] = l;
            split_tf32(wv.y, h, l); Wh[(k4 + 1) * WST + o] = h; Wl[(k4 + 1) * WST + o] = l;
            split_tf32(wv.z, h, l); Wh[(k4 + 2) * WST + o] = h; Wl[(k4 + 2) * WST + o] = l;
            split_tf32(wv.w, h, l); Wh[(k4 + 3) * WST + o] = h; Wl[(k4 + 3) * WST + o] = l;
        }
        // X tile: 16k x 64n -> [k][n] hi/lo
        #pragma unroll
        for (int j = 0; j < 2; j++) {
            int idx = tid + j * 128;
            int k = idx >> 4, n4 = (idx & 15) * 4;
            float4 xv = *(const float4*)&xb[(size_t)(kb + k) * NPIX + nb + n4];
            unsigned h0, l0, h1, l1, h2, l2, h3, l3;
            split_tf32(xv.x, h0, l0); split_tf32(xv.y, h1, l1);
            split_tf32(xv.z, h2, l2); split_tf32(xv.w, h3, l3);
            *(uint4*)&Xh[k * XST + n4] = make_uint4(h0, h1, h2, h3);
            *(uint4*)&Xl[k * XST + n4] = make_uint4(l0, l1, l2, l3);
        }
        __syncthreads();

        #pragma unroll
        for (int kf = 0; kf < 2; kf++) {
            const int r0 = kf * 8 + t, r1 = r0 + 4;
            unsigned ah[2][4], al[2][4];
            #pragma unroll
            for (int mf = 0; mf < 2; mf++) {
                const int wo = warp * 32 + mf * 16;
                ah[mf][0] = Wh[r0 * WST + wo + g];     al[mf][0] = Wl[r0 * WST + wo + g];
                ah[mf][1] = Wh[r0 * WST + wo + g + 8]; al[mf][1] = Wl[r0 * WST + wo + g + 8];
                ah[mf][2] = Wh[r1 * WST + wo + g];     al[mf][2] = Wl[r1 * WST + wo + g];
                ah[mf][3] = Wh[r1 * WST + wo + g + 8]; al[mf][3] = Wl[r1 * WST + wo + g + 8];
            }
            #pragma unroll
            for (int nt = 0; nt < 8; nt++) {
                unsigned b0h = Xh[r0 * XST + nt * 8 + g];
                unsigned b1h = Xh[r1 * XST + nt * 8 + g];
                unsigned b0l = Xl[r0 * XST + nt * 8 + g];
                unsigned b1l = Xl[r1 * XST + nt * 8 + g];
                mma_tf32(acc[0][nt], ah[0], b0h, b1h);
                mma_tf32(acc[0][nt], ah[0], b0l, b1l);
                mma_tf32(acc[0][nt], al[0], b0h, b1h);
                mma_tf32(acc[1][nt], ah[1], b0h, b1h);
                mma_tf32(acc[1][nt], ah[1], b0l, b1l);
                mma_tf32(acc[1][nt], al[1], b0h, b1h);
            }
        }
    }

    // Epilogue: route to g_q/g_k/g_v in [bh][d][n] layout
    #pragma unroll
    for (int mf = 0; mf < 2; mf++) {
        #pragma unroll
        for (int r = 0; r < 2; r++) {
            int o   = ob + warp * 32 + mf * 16 + r * 8 + g;
            int sec = o >> 7;            // uniform per block (ob multiple of 128)
            int oc  = o & 127;
            int bh  = b * NHEADS + (oc >> 5);
            int d   = oc & 31;
            float mult = (sec == 0) ? QSCALE : 1.0f;
            float* dst = (sec == 0) ? g_q : (sec == 1) ? g_k : g_v;
            float* row = dst + (size_t)(bh * 32 + d) * NPIX + nb + 2 * t;
            #pragma unroll
            for (int nt = 0; nt < 8; nt++)
                *(float2*)&row[nt * 8] = make_float2(acc[mf][nt][2 * r] * mult,
                                                     acc[mf][nt][2 * r + 1] * mult);
        }
    }
}

// ---------------------------------------------------------------------------
// Kernel 2: flash attention, QTILE=128 (warp = 32 queries), KTILE=64.
// P transpose (C-frag -> A-frag) via shfl, no smem P staging.
// ---------------------------------------------------------------------------
#define KTILE 64
#define QTILE 128
#define KST 72    // K arrays: S-phase loads bank 8t+g -> conflict-free
#define VST 68    // V arrays: PV loads bank 4g+t -> conflict-free

__global__ void __launch_bounds__(128) attn_mma_kernel()
{
    __shared__ __align__(16) unsigned sbuf[2 * 32 * KST + 2 * 32 * VST];
    unsigned* Ksh = sbuf;
    unsigned* Ksl = sbuf + 32 * KST;
    unsigned* Vsh = sbuf + 2 * 32 * KST;
    unsigned* Vsl = Vsh + 32 * VST;

    const int bh    = blockIdx.y;
    const int qbase = blockIdx.x * QTILE;
    const int tid   = threadIdx.x;
    const int warp  = tid >> 5;
    const int lane  = tid & 31;
    const int g     = lane >> 2;
    const int t     = lane & 3;
    const int src0  = (lane & ~3) | (t >> 1);   // P-transpose source lanes
    const int src1  = src0 + 2;

    const float* qp = g_q + (size_t)bh * DHEAD * NPIX;
    const float* kp = g_k + (size_t)bh * DHEAD * NPIX;
    const float* vp = g_v + (size_t)bh * DHEAD * NPIX;

    // Resident Q fragments (2 m-frags, hi/lo)
    unsigned qh[2][4][4], ql[2][4][4];
    const int qrow0 = qbase + warp * 32 + g;
    #pragma unroll
    for (int mf = 0; mf < 2; mf++) {
        const int rA = qrow0 + mf * 16, rB = rA + 8;
        #pragma unroll
        for (int kf = 0; kf < 4; kf++) {
            int d0 = kf * 8 + t, d1 = d0 + 4;
            split_tf32(qp[(size_t)d0 * NPIX + rA], qh[mf][kf][0], ql[mf][kf][0]);
            split_tf32(qp[(size_t)d0 * NPIX + rB], qh[mf][kf][1], ql[mf][kf][1]);
            split_tf32(qp[(size_t)d1 * NPIX + rA], qh[mf][kf][2], ql[mf][kf][2]);
            split_tf32(qp[(size_t)d1 * NPIX + rB], qh[mf][kf][3], ql[mf][kf][3]);
        }
    }

    float o[2][4][4] = {};
    float mst[2][2], lst[2][2];
    #pragma unroll
    for (int mf = 0; mf < 2; mf++) {
        mst[mf][0] = -CUDART_INF_F; mst[mf][1] = -CUDART_INF_F;
        lst[mf][0] = 0.f;           lst[mf][1] = 0.f;
    }

    for (int kb = 0; kb < NPIX; kb += KTILE) {
        __syncthreads();   // previous PV reads of Vs complete
        #pragma unroll
        for (int i = tid; i < 32 * 16; i += 128) {
            int d = i >> 4, j4 = (i & 15) * 4;
            float4 kv = *(const float4*)&kp[(size_t)d * NPIX + kb + j4];
            float4 vv = *(const float4*)&vp[(size_t)d * NPIX + kb + j4];
            unsigned h0, l0, h1, l1, h2, l2, h3, l3;
            split_tf32(kv.x, h0, l0); split_tf32(kv.y, h1, l1);
            split_tf32(kv.z, h2, l2); split_tf32(kv.w, h3, l3);
            *(uint4*)&Ksh[d * KST + j4] = make_uint4(h0, h1, h2, h3);
            *(uint4*)&Ksl[d * KST + j4] = make_uint4(l0, l1, l2, l3);
            split_tf32(vv.x, h0, l0); split_tf32(vv.y, h1, l1);
            split_tf32(vv.z, h2, l2); split_tf32(vv.w, h3, l3);
            *(uint4*)&Vsh[d * VST + j4] = make_uint4(h0, h1, h2, h3);
            *(uint4*)&Vsl[d * VST + j4] = make_uint4(l0, l1, l2, l3);
        }
        __syncthreads();

        // ---- S = Q K^T  (32 x 64 per warp): each B-load feeds 6 mmas ----
        float s[2][8][4];
        #pragma unroll
        for (int mf = 0; mf < 2; mf++)
            #pragma unroll
            for (int nt = 0; nt < 8; nt++)
                s[mf][nt][0] = s[mf][nt][1] = s[mf][nt][2] = s[mf][nt][3] = 0.f;
        #pragma unroll
        for (int kf = 0; kf < 4; kf++) {
            const int r0 = kf * 8 + t, r1 = r0 + 4;
            #pragma unroll
            for (int nt = 0; nt < 8; nt++) {
                unsigned b0h = Ksh[r0 * KST + nt * 8 + g];
                unsigned b1h = Ksh[r1 * KST + nt * 8 + g];
                unsigned b0l = Ksl[r0 * KST + nt * 8 + g];
                unsigned b1l = Ksl[r1 * KST + nt * 8 + g];
                mma_tf32(s[0][nt], qh[0][kf], b0h, b1h);
                mma_tf32(s[0][nt], qh[0][kf], b0l, b1l);
                mma_tf32(s[0][nt], ql[0][kf], b0h, b1h);
                mma_tf32(s[1][nt], qh[1][kf], b0h, b1h);
                mma_tf32(s[1][nt], qh[1][kf], b0l, b1l);
                mma_tf32(s[1][nt], ql[1][kf], b0h, b1h);
            }
        }

        // ---- online softmax per m-frag ----
        #pragma unroll
        for (int mf = 0; mf < 2; mf++) {
            float tA = -CUDART_INF_F, tB = -CUDART_INF_F;
            #pragma unroll
            for (int nt = 0; nt < 8; nt++) {
                tA = fmaxf(tA, fmaxf(s[mf][nt][0], s[mf][nt][1]));
                tB = fmaxf(tB, fmaxf(s[mf][nt][2], s[mf][nt][3]));
            }
            tA = rmax4(tA); tB = rmax4(tB);
            float mAn = fmaxf(mst[mf][0], tA), mBn = fmaxf(mst[mf][1], tB);
            float aA = __expf(mst[mf][0] - mAn), aB = __expf(mst[mf][1] - mBn);
            float sumA = 0.f, sumB = 0.f;
            #pragma unroll
            for (int nt = 0; nt < 8; nt++) {
                s[mf][nt][0] = __expf(s[mf][nt][0] - mAn);
                s[mf][nt][1] = __expf(s[mf][nt][1] - mAn);
                s[mf][nt][2] = __expf(s[mf][nt][2] - mBn);
                s[mf][nt][3] = __expf(s[mf][nt][3] - mBn);
                sumA += s[mf][nt][0] + s[mf][nt][1];
                sumB += s[mf][nt][2] + s[mf][nt][3];
            }
            sumA = rsum4(sumA); sumB = rsum4(sumB);
            lst[mf][0] = lst[mf][0] * aA + sumA;
            lst[mf][1] = lst[mf][1] * aB + sumB;
            mst[mf][0] = mAn; mst[mf][1] = mBn;
            #pragma unroll
            for (int nt = 0; nt < 4; nt++) {
                o[mf][nt][0] *= aA; o[mf][nt][1] *= aA;
                o[mf][nt][2] *= aB; o[mf][nt][3] *= aB;
            }
        }

        // ---- O += P V: P transposed C->A fragment via shfl ----
        #pragma unroll
        for (int kf = 0; kf < 8; kf++) {
            unsigned pah[2][4], pal[2][4];
            #pragma unroll
            for (int mf = 0; mf < 2; mf++) {
                float p00 = __shfl_sync(0xffffffffu, s[mf][kf][0], src0);
                float p01 = __shfl_sync(0xffffffffu, s[mf][kf][1], src0);
                float p02 = __shfl_sync(0xffffffffu, s[mf][kf][0], src1);
                float p03 = __shfl_sync(0xffffffffu, s[mf][kf][1], src1);
                float p10 = __shfl_sync(0xffffffffu, s[mf][kf][2], src0);
                float p11 = __shfl_sync(0xffffffffu, s[mf][kf][3], src0);
                float p12 = __shfl_sync(0xffffffffu, s[mf][kf][2], src1);
                float p13 = __shfl_sync(0xffffffffu, s[mf][kf][3], src1);
                float a0 = (t & 1) ? p01 : p00;   // P[rowA][kf*8+t]
                float a2 = (t & 1) ? p03 : p02;   // P[rowA][kf*8+t+4]
                float a1 = (t & 1) ? p11 : p10;   // P[rowB][kf*8+t]
                float a3 = (t & 1) ? p13 : p12;   // P[rowB][kf*8+t+4]
                split_tf32(a0, pah[mf][0], pal[mf][0]);
                split_tf32(a1, pah[mf][1], pal[mf][1]);
                split_tf32(a2, pah[mf][2], pal[mf][2]);
                split_tf32(a3, pah[mf][3], pal[mf][3]);
            }
            #pragma unroll
            for (int nt = 0; nt < 4; nt++) {
                unsigned b0h = Vsh[(nt * 8 + g) * VST + kf * 8 + t];
                unsigned b1h = Vsh[(nt * 8 + g) * VST + kf * 8 + t + 4];
                unsigned b0l = Vsl[(nt * 8 + g) * VST + kf * 8 + t];
                unsigned b1l = Vsl[(nt * 8 + g) * VST + kf * 8 + t + 4];
                mma_tf32(o[0][nt], pah[0], b0h, b1h);
                mma_tf32(o[0][nt], pah[0], b0l, b1l);
                mma_tf32(o[0][nt], pal[0], b0h, b1h);
                mma_tf32(o[1][nt], pah[1], b0h, b1h);
                mma_tf32(o[1][nt], pah[1], b0l, b1l);
                mma_tf32(o[1][nt], pal[1], b0h, b1h);
            }
        }
    }

    // ---- epilogue: normalize + store to g_o [d][n] ----
    float* op = g_o + (size_t)bh * DHEAD * NPIX;
    #pragma unroll
    for (int mf = 0; mf < 2; mf++) {
        const float iA = 1.0f / lst[mf][0], iB = 1.0f / lst[mf][1];
        const int rA = qrow0 + mf * 16, rB = rA + 8;
        #pragma unroll
        for (int nt = 0; nt < 4; nt++) {
            int d0 = nt * 8 + 2 * t, d1 = d0 + 1;
            op[(size_t)d0 * NPIX + rA] = o[mf][nt][0] * iA;
            op[(size_t)d1 * NPIX + rA] = o[mf][nt][1] * iA;
            op[(size_t)d0 * NPIX + rB] = o[mf][nt][2] * iB;
            op[(size_t)d1 * NPIX + rB] = o[mf][nt][3] * iB;
        }
    }
}

// ---------------------------------------------------------------------------
// Kernel 3: output projection + bias.  M-tile 128, N-tile 64, k-step 16.
// ---------------------------------------------------------------------------
__global__ void __launch_bounds__(128) proj_mma_kernel(const float* __restrict__ w,
                                                       const float* __restrict__ bias,
                                                       float* __restrict__ out)
{
    __shared__ __align__(16) unsigned Wh[16 * WST], Wl[16 * WST];
    __shared__ __align__(16) unsigned Xh[16 * XST], Xl[16 * XST];

    const int b  = blockIdx.z;
    const int ob = blockIdx.y * 128;
    const int nb = blockIdx.x * 64;
    const int tid  = threadIdx.x;
    const int warp = tid >> 5;
    const int lane = tid & 31;
    const int g = lane >> 2, t = lane & 3;

    const float* gb = g_o + (size_t)b * HID * NPIX;

    float acc[2][8][4] = {};

    for (int kb = 0; kb < HID; kb += 16) {
        __syncthreads();
        #pragma unroll
        for (int j = 0; j < 4; j++) {
            int idx = tid + j * 128;
            int o = idx >> 2, k4 = (idx & 3) * 4;
            float4 wv = *(const float4*)&w[(ob + o) * HID + kb + k4];
            unsigned h, l;
            split_tf32(wv.x, h, l); Wh[(k4 + 0) * WST + o] = h; Wl[(k4 + 0) * WST + o] = l;
            split_tf32(wv.y, h, l); Wh[(k4 + 1) * WST + o] = h; Wl[(k4 + 1) * WST + o] = l;
            split_tf32(wv.z, h, l); Wh[(k4 + 2) * WST + o] = h; Wl[(k4 + 2) * WST + o] = l;
            split_tf32(wv.w, h, l); Wh[(k4 + 3) * WST + o] = h; Wl[(k4 + 3) * WST + o] = l;
        }
        #pragma unroll
        for (int j = 0; j < 2; j++) {
            int idx = tid + j * 128;
            int k = idx >> 4, n4 = (idx & 15) * 4;
            float4 xv = *(const float4*)&gb[(size_t)(kb + k) * NPIX + nb + n4];
            unsigned h0, l0, h1, l1, h2, l2, h3, l3;
            split_tf32(xv.x, h0, l0); split_tf32(xv.y, h1, l1);
            split_tf32(xv.z, h2, l2); split_tf32(xv.w, h3, l3);
            *(uint4*)&Xh[k * XST + n4] = make_uint4(h0, h1, h2, h3);
            *(uint4*)&Xl[k * XST + n4] = make_uint4(l0, l1, l2, l3);
        }
        __syncthreads();

        #pragma unroll
        for (int kf = 0; kf < 2; kf++) {
            const int r0 = kf * 8 + t, r1 = r0 + 4;
            unsigned ah[2][4], al[2][4];
            #pragma unroll
            for (int mf = 0; mf < 2; mf++) {
                const int wo = warp * 32 + mf * 16;
                ah[mf][0] = Wh[r0 * WST + wo + g];     al[mf][0] = Wl[r0 * WST + wo + g];
                ah[mf][1] = Wh[r0 * WST + wo + g + 8]; al[mf][1] = Wl[r0 * WST + wo + g + 8];
                ah[mf][2] = Wh[r1 * WST + wo + g];     al[mf][2] = Wl[r1 * WST + wo + g];
                ah[mf][3] = Wh[r1 * WST + wo + g + 8]; al[mf][3] = Wl[r1 * WST + wo + g + 8];
            }
            #pragma unroll
            for (int nt = 0; nt < 8; nt++) {
                unsigned b0h = Xh[r0 * XST + nt * 8 + g];
                unsigned b1h = Xh[r1 * XST + nt * 8 + g];
                unsigned b0l = Xl[r0 * XST + nt * 8 + g];
                unsigned b1l = Xl[r1 * XST + nt * 8 + g];
                mma_tf32(acc[0][nt], ah[0], b0h, b1h);
                mma_tf32(acc[0][nt], ah[0], b0l, b1l);
                mma_tf32(acc[0][nt], al[0], b0h, b1h);
                mma_tf32(acc[1][nt], ah[1], b0h, b1h);
                mma_tf32(acc[1][nt], ah[1], b0l, b1l);
                mma_tf32(acc[1][nt], al[1], b0h, b1h);
            }
        }
    }

    #pragma unroll
    for (int mf = 0; mf < 2; mf++) {
        #pragma unroll
        for (int r = 0; r < 2; r++) {
            int o = ob + warp * 32 + mf * 16 + r * 8 + g;
            float bv = bias[o];
            float* row = out + (size_t)(b * CIN + o) * NPIX + nb + 2 * t;
            #pragma unroll
            for (int nt = 0; nt < 8; nt++)
                *(float2*)&row[nt * 8] = make_float2(acc[mf][nt][2 * r] + bv,
                                                     acc[mf][nt][2 * r + 1] + bv);
        }
    }
}

// ---------------------------------------------------------------------------
extern "C" void kernel_launch(void* const* d_in, const int* in_sizes, int n_in,
                              void* d_out, int out_size)
{
    const float* x     = (const float*)d_in[0];  // [8,256,48,48]
    const float* w_qkv = (const float*)d_in[1];  // [384,256]
    const float* w_out = (const float*)d_in[2];  // [256,128]
    const float* b_out = (const float*)d_in[3];  // [256]
    float* out = (float*)d_out;                  // [8,256,48,48]

    {
        dim3 grid(NPIX / 64, (3 * HID) / 128, BATCH);  // 36 x 3 x 8
        qkv_mma_kernel<<<grid, 128>>>(x, w_qkv);
    }
    {
        dim3 grid(NPIX / QTILE, BATCH * NHEADS);        // 18 x 32
        attn_mma_kernel<<<grid, 128>>>();
    }
    {
        dim3 grid(NPIX / 64, CIN / 128, BATCH);         // 36 x 2 x 8
        proj_mma_kernel<<<grid, 128>>>(w_out, b_out, out);
    }
}

// round 15
// speedup vs baseline: 3.7339x; 1.7584x over previous
#include <cuda_runtime.h>
#include <cuda_bf16.h>
#include <math_constants.h>

// Problem constants
#define NPIX 2304          // 48*48
#define CIN  256
#define HID  128           // heads*dim_head
#define NHEADS 4
#define DHEAD 32
#define BATCH 8
#define QSCALE 0.17677669529663687f   // 1/sqrt(32)

// Scratch.  NOTE layouts:
//   g_q, g_k : [bh][n][32]   (pixel-major, 32 dims contiguous)  -- for bf16 k-packing
//   g_v, g_o : [bh(c)][.][n] (dim-major, pixels contiguous)
__device__ float g_q[BATCH * HID * NPIX];
__device__ float g_k[BATCH * HID * NPIX];
__device__ float g_v[BATCH * HID * NPIX];
__device__ float g_o[BATCH * HID * NPIX];

// ---------------------------------------------------------------------------
// Helpers: bf16x2 packing, fp32 -> (bf16 hi, bf16 lo) split, m16n8k16 mma
// ---------------------------------------------------------------------------
__device__ __forceinline__ unsigned pack_bf16(float lo, float hi)
{
    unsigned r;
    asm("cvt.rn.bf16x2.f32 %0, %1, %2;" : "=r"(r) : "f"(hi), "f"(lo));
    return r;   // low 16 bits = lo (smaller k index), high = hi
}

__device__ __forceinline__ void split2_bf16(float v0, float v1,
                                            unsigned& h, unsigned& l)
{
    h = pack_bf16(v0, v1);
    float h0 = __uint_as_float(h << 16);
    float h1 = __uint_as_float(h & 0xffff0000u);
    l = pack_bf16(v0 - h0, v1 - h1);
}

__device__ __forceinline__ void mma_bf16(float d[4], const unsigned a[4],
                                         unsigned b0, unsigned b1)
{
    asm volatile(
        "mma.sync.aligned.m16n8k16.row.col.f32.bf16.bf16.f32 "
        "{%0,%1,%2,%3}, {%4,%5,%6,%7}, {%8,%9}, {%0,%1,%2,%3};\n"
        : "+f"(d[0]), "+f"(d[1]), "+f"(d[2]), "+f"(d[3])
        : "r"(a[0]), "r"(a[1]), "r"(a[2]), "r"(a[3]), "r"(b0), "r"(b1));
}

__device__ __forceinline__ float rmax4(float v) {
    v = fmaxf(v, __shfl_xor_sync(0xffffffffu, v, 1));
    v = fmaxf(v, __shfl_xor_sync(0xffffffffu, v, 2));
    return v;
}
__device__ __forceinline__ float rsum4(float v) {
    v += __shfl_xor_sync(0xffffffffu, v, 1);
    v += __shfl_xor_sync(0xffffffffu, v, 2);
    return v;
}

// ---------------------------------------------------------------------------
// GEMM core (shared by qkv and proj):  C[128 o-rows, 64 n-cols] per block.
// W in smem [o][k2] stride 12 (pairs packed along k); X in smem [k2][n]
// stride 72 (pairs packed along k, transposed at load).  k-step 16.
// ---------------------------------------------------------------------------
#define WST2 12
#define NST2 72

// ---------------------------------------------------------------------------
// Kernel 1: QKV projection, bf16x3 mma.  C[384,2304] = W[384,256] @ X[256,2304]
// ---------------------------------------------------------------------------
__global__ void __launch_bounds__(128) qkv_mma_kernel(const float* __restrict__ x,
                                                      const float* __restrict__ w)
{
    __shared__ __align__(16) unsigned Wh2[128 * WST2], Wl2[128 * WST2];
    __shared__ __align__(16) unsigned Xh2[8 * NST2],  Xl2[8 * NST2];

    const int b  = blockIdx.z;
    const int ob = blockIdx.y * 128;
    const int nb = blockIdx.x * 64;
    const int tid  = threadIdx.x;
    const int warp = tid >> 5;
    const int lane = tid & 31;
    const int g = lane >> 2, t = lane & 3;

    const float* xb = x + (size_t)b * CIN * NPIX;

    float acc[2][8][4] = {};

    for (int kb = 0; kb < CIN; kb += 16) {
        __syncthreads();
        // W tile: 128 o x 16 k  -> Wh2[o][k2]
        #pragma unroll
        for (int j = 0; j < 4; j++) {
            int i = tid + j * 128;
            int o = i >> 2, k4 = (i & 3) * 4;
            float4 wv = *(const float4*)&w[(ob + o) * CIN + kb + k4];
            unsigned h0, l0, h1, l1;
            split2_bf16(wv.x, wv.y, h0, l0);
            split2_bf16(wv.z, wv.w, h1, l1);
            *(uint2*)&Wh2[o * WST2 + k4 / 2] = make_uint2(h0, h1);
            *(uint2*)&Wl2[o * WST2 + k4 / 2] = make_uint2(l0, l1);
        }
        // X tile: 16 k x 64 n, transposed pack -> Xh2[k2][n]
        #pragma unroll
        for (int s = 0; s < 4; s++) {
            int i = tid + s * 128;
            int n = i & 63, k2 = i >> 6;
            const float* base = &xb[(size_t)(kb + 2 * k2) * NPIX + nb + n];
            unsigned h, l;
            split2_bf16(base[0], base[NPIX], h, l);
            Xh2[k2 * NST2 + n] = h;
            Xl2[k2 * NST2 + n] = l;
        }
        __syncthreads();

        unsigned ah[2][4], al[2][4];
        #pragma unroll
        for (int mf = 0; mf < 2; mf++) {
            const int wo = warp * 32 + mf * 16;
            ah[mf][0] = Wh2[(wo + g)     * WST2 + t];     al[mf][0] = Wl2[(wo + g)     * WST2 + t];
            ah[mf][1] = Wh2[(wo + 8 + g) * WST2 + t];     al[mf][1] = Wl2[(wo + 8 + g) * WST2 + t];
            ah[mf][2] = Wh2[(wo + g)     * WST2 + t + 4]; al[mf][2] = Wl2[(wo + g)     * WST2 + t + 4];
            ah[mf][3] = Wh2[(wo + 8 + g) * WST2 + t + 4]; al[mf][3] = Wl2[(wo + 8 + g) * WST2 + t + 4];
        }
        #pragma unroll
        for (int nt = 0; nt < 8; nt++) {
            unsigned b0h = Xh2[t       * NST2 + nt * 8 + g];
            unsigned b1h = Xh2[(t + 4) * NST2 + nt * 8 + g];
            unsigned b0l = Xl2[t       * NST2 + nt * 8 + g];
            unsigned b1l = Xl2[(t + 4) * NST2 + nt * 8 + g];
            mma_bf16(acc[0][nt], ah[0], b0h, b1h);
            mma_bf16(acc[0][nt], ah[0], b0l, b1l);
            mma_bf16(acc[0][nt], al[0], b0h, b1h);
            mma_bf16(acc[1][nt], ah[1], b0h, b1h);
            mma_bf16(acc[1][nt], ah[1], b0l, b1l);
            mma_bf16(acc[1][nt], al[1], b0h, b1h);
        }
    }

    // Epilogue.  sec uniform per block (ob multiple of 128).
    const int sec = ob >> 7;   // 0=q, 1=k, 2=v
    #pragma unroll
    for (int mf = 0; mf < 2; mf++) {
        #pragma unroll
        for (int r = 0; r < 2; r++) {
            int o  = ob + warp * 32 + mf * 16 + r * 8 + g;
            int oc = o & 127;
            int bh = b * NHEADS + (oc >> 5);
            int d  = oc & 31;
            if (sec == 2) {
                float* row = g_v + (size_t)(bh * 32 + d) * NPIX + nb + 2 * t;
                #pragma unroll
                for (int nt = 0; nt < 8; nt++)
                    *(float2*)&row[nt * 8] = make_float2(acc[mf][nt][2 * r],
                                                         acc[mf][nt][2 * r + 1]);
            } else {
                const float mult = (sec == 0) ? QSCALE : 1.0f;
                float* dst = (sec == 0) ? g_q : g_k;
                float* base = dst + (size_t)bh * NPIX * 32 + d;
                #pragma unroll
                for (int nt = 0; nt < 8; nt++) {
                    int n0 = nb + nt * 8 + 2 * t;
                    base[(size_t)n0 * 32]       = acc[mf][nt][2 * r] * mult;
                    base[(size_t)(n0 + 1) * 32] = acc[mf][nt][2 * r + 1] * mult;
                }
            }
        }
    }
}

// ---------------------------------------------------------------------------
// Kernel 2: flash attention, bf16x3 mma, QTILE=128 (warp = 32 q), KTILE=64.
// K smem [key][d2] stride 20; V smem [d][key2] stride 36.  P A-fragments are
// the S C-fragments directly (m16n8k16 alignment) -- no shuffles, no staging.
// ---------------------------------------------------------------------------
#define KTILE 64
#define QTILE 128
#define KST2  20
#define VST2  36

__global__ void __launch_bounds__(128) attn_mma_kernel()
{
    __shared__ __align__(16) unsigned Ksh[64 * KST2], Ksl[64 * KST2];
    __shared__ __align__(16) unsigned Vsh[32 * VST2], Vsl[32 * VST2];

    const int bh    = blockIdx.y;
    const int qbase = blockIdx.x * QTILE;
    const int tid   = threadIdx.x;
    const int warp  = tid >> 5;
    const int lane  = tid & 31;
    const int g     = lane >> 2;
    const int t     = lane & 3;

    const float* qp = g_q + (size_t)bh * NPIX * 32;   // [n][d]
    const float* kp = g_k + (size_t)bh * NPIX * 32;   // [n][d]
    const float* vp = g_v + (size_t)bh * DHEAD * NPIX; // [d][n]

    // Resident Q A-fragments (2 m-frags x 2 k-chunks), hi/lo
    unsigned qh[2][2][4], ql[2][2][4];
    const int qrow0 = qbase + warp * 32 + g;
    #pragma unroll
    for (int mf = 0; mf < 2; mf++) {
        const int rA = qrow0 + mf * 16, rB = rA + 8;
        #pragma unroll
        for (int kf = 0; kf < 2; kf++) {
            float2 v0 = *(const float2*)&qp[(size_t)rA * 32 + 16 * kf + 2 * t];
            float2 v1 = *(const float2*)&qp[(size_t)rB * 32 + 16 * kf + 2 * t];
            float2 v2 = *(const float2*)&qp[(size_t)rA * 32 + 16 * kf + 2 * t + 8];
            float2 v3 = *(const float2*)&qp[(size_t)rB * 32 + 16 * kf + 2 * t + 8];
            split2_bf16(v0.x, v0.y, qh[mf][kf][0], ql[mf][kf][0]);
            split2_bf16(v1.x, v1.y, qh[mf][kf][1], ql[mf][kf][1]);
            split2_bf16(v2.x, v2.y, qh[mf][kf][2], ql[mf][kf][2]);
            split2_bf16(v3.x, v3.y, qh[mf][kf][3], ql[mf][kf][3]);
        }
    }

    float o[2][4][4] = {};
    float mst[2][2], lst[2][2];
    #pragma unroll
    for (int mf = 0; mf < 2; mf++) {
        mst[mf][0] = -CUDART_INF_F; mst[mf][1] = -CUDART_INF_F;
        lst[mf][0] = 0.f;           lst[mf][1] = 0.f;
    }

    for (int kb = 0; kb < NPIX; kb += KTILE) {
        __syncthreads();   // previous PV reads of Vs complete
        // K tile: 64 keys x 32 d from [n][d] -> Ksh[key][d2]
        #pragma unroll
        for (int s = 0; s < 4; s++) {
            int i = tid + s * 128;
            int j = i >> 3, d4 = (i & 7) * 4;
            float4 kv = *(const float4*)&kp[(size_t)(kb + j) * 32 + d4];
            unsigned h0, l0, h1, l1;
            split2_bf16(kv.x, kv.y, h0, l0);
            split2_bf16(kv.z, kv.w, h1, l1);
            *(uint2*)&Ksh[j * KST2 + d4 / 2] = make_uint2(h0, h1);
            *(uint2*)&Ksl[j * KST2 + d4 / 2] = make_uint2(l0, l1);
        }
        // V tile: 32 d x 64 keys from [d][n] -> Vsh[d][key2]
        #pragma unroll
        for (int s = 0; s < 4; s++) {
            int i = tid + s * 128;
            int d = i >> 4, n4 = (i & 15) * 4;
            float4 vv = *(const float4*)&vp[(size_t)d * NPIX + kb + n4];
            unsigned h0, l0, h1, l1;
            split2_bf16(vv.x, vv.y, h0, l0);
            split2_bf16(vv.z, vv.w, h1, l1);
            *(uint2*)&Vsh[d * VST2 + n4 / 2] = make_uint2(h0, h1);
            *(uint2*)&Vsl[d * VST2 + n4 / 2] = make_uint2(l0, l1);
        }
        __syncthreads();

        // ---- S = Q K^T (32 x 64 per warp), bf16x3 ----
        float s[2][8][4];
        #pragma unroll
        for (int mf = 0; mf < 2; mf++)
            #pragma unroll
            for (int nt = 0; nt < 8; nt++)
                s[mf][nt][0] = s[mf][nt][1] = s[mf][nt][2] = s[mf][nt][3] = 0.f;
        #pragma unroll
        for (int kf = 0; kf < 2; kf++) {
            #pragma unroll
            for (int nt = 0; nt < 8; nt++) {
                const int row = (nt * 8 + g) * KST2;
                unsigned b0h = Ksh[row + 8 * kf + t];
                unsigned b1h = Ksh[row + 8 * kf + t + 4];
                unsigned b0l = Ksl[row + 8 * kf + t];
                unsigned b1l = Ksl[row + 8 * kf + t + 4];
                mma_bf16(s[0][nt], qh[0][kf], b0h, b1h);
                mma_bf16(s[0][nt], qh[0][kf], b0l, b1l);
                mma_bf16(s[0][nt], ql[0][kf], b0h, b1h);
                mma_bf16(s[1][nt], qh[1][kf], b0h, b1h);
                mma_bf16(s[1][nt], qh[1][kf], b0l, b1l);
                mma_bf16(s[1][nt], ql[1][kf], b0h, b1h);
            }
        }

        // ---- online softmax per m-frag ----
        #pragma unroll
        for (int mf = 0; mf < 2; mf++) {
            float tA = -CUDART_INF_F, tB = -CUDART_INF_F;
            #pragma unroll
            for (int nt = 0; nt < 8; nt++) {
                tA = fmaxf(tA, fmaxf(s[mf][nt][0], s[mf][nt][1]));
                tB = fmaxf(tB, fmaxf(s[mf][nt][2], s[mf][nt][3]));
            }
            tA = rmax4(tA); tB = rmax4(tB);
            float mAn = fmaxf(mst[mf][0], tA), mBn = fmaxf(mst[mf][1], tB);
            float aA = __expf(mst[mf][0] - mAn), aB = __expf(mst[mf][1] - mBn);
            float sumA = 0.f, sumB = 0.f;
            #pragma unroll
            for (int nt = 0; nt < 8; nt++) {
                s[mf][nt][0] = __expf(s[mf][nt][0] - mAn);
                s[mf][nt][1] = __expf(s[mf][nt][1] - mAn);
                s[mf][nt][2] = __expf(s[mf][nt][2] - mBn);
                s[mf][nt][3] = __expf(s[mf][nt][3] - mBn);
                sumA += s[mf][nt][0] + s[mf][nt][1];
                sumB += s[mf][nt][2] + s[mf][nt][3];
            }
            sumA = rsum4(sumA); sumB = rsum4(sumB);
            lst[mf][0] = lst[mf][0] * aA + sumA;
            lst[mf][1] = lst[mf][1] * aB + sumB;
            mst[mf][0] = mAn; mst[mf][1] = mBn;
            #pragma unroll
            for (int nt = 0; nt < 4; nt++) {
                o[mf][nt][0] *= aA; o[mf][nt][1] *= aA;
                o[mf][nt][2] *= aB; o[mf][nt][3] *= aB;
            }
        }

        // ---- O += P V: P A-fragments come straight from S C-fragments ----
        #pragma unroll
        for (int kf = 0; kf < 4; kf++) {           // key chunks of 16
            unsigned pah[2][4], pal[2][4];
            #pragma unroll
            for (int mf = 0; mf < 2; mf++) {
                split2_bf16(s[mf][2*kf][0],   s[mf][2*kf][1],   pah[mf][0], pal[mf][0]);
                split2_bf16(s[mf][2*kf][2],   s[mf][2*kf][3],   pah[mf][1], pal[mf][1]);
                split2_bf16(s[mf][2*kf+1][0], s[mf][2*kf+1][1], pah[mf][2], pal[mf][2]);
                split2_bf16(s[mf][2*kf+1][2], s[mf][2*kf+1][3], pah[mf][3], pal[mf][3]);
            }
            #pragma unroll
            for (int nt = 0; nt < 4; nt++) {       // dim chunks of 8
                const int row = (nt * 8 + g) * VST2;
                unsigned b0h = Vsh[row + 8 * kf + t];
                unsigned b1h = Vsh[row + 8 * kf + t + 4];
                unsigned b0l = Vsl[row + 8 * kf + t];
                unsigned b1l = Vsl[row + 8 * kf + t + 4];
                mma_bf16(o[0][nt], pah[0], b0h, b1h);
                mma_bf16(o[0][nt], pah[0], b0l, b1l);
                mma_bf16(o[0][nt], pal[0], b0h, b1h);
                mma_bf16(o[1][nt], pah[1], b0h, b1h);
                mma_bf16(o[1][nt], pah[1], b0l, b1l);
                mma_bf16(o[1][nt], pal[1], b0h, b1h);
            }
        }
    }

    // ---- epilogue: normalize + store to g_o [c][n] ----
    float* op = g_o + (size_t)bh * DHEAD * NPIX;
    #pragma unroll
    for (int mf = 0; mf < 2; mf++) {
        const float iA = 1.0f / lst[mf][0], iB = 1.0f / lst[mf][1];
        const int rA = qrow0 + mf * 16, rB = rA + 8;
        #pragma unroll
        for (int nt = 0; nt < 4; nt++) {
            int d0 = nt * 8 + 2 * t, d1 = d0 + 1;
            op[(size_t)d0 * NPIX + rA] = o[mf][nt][0] * iA;
            op[(size_t)d1 * NPIX + rA] = o[mf][nt][1] * iA;
            op[(size_t)d0 * NPIX + rB] = o[mf][nt][2] * iB;
            op[(size_t)d1 * NPIX + rB] = o[mf][nt][3] * iB;
        }
    }
}

// ---------------------------------------------------------------------------
// Kernel 3: output projection, bf16x3 mma + bias.
// C[256,2304] = W_out[256,128] @ G_o[b][128,2304] + b_out
// ---------------------------------------------------------------------------
__global__ void __launch_bounds__(128) proj_mma_kernel(const float* __restrict__ w,
                                                       const float* __restrict__ bias,
                                                       float* __restrict__ out)
{
    __shared__ __align__(16) unsigned Wh2[128 * WST2], Wl2[128 * WST2];
    __shared__ __align__(16) unsigned Xh2[8 * NST2],  Xl2[8 * NST2];

    const int b  = blockIdx.z;
    const int ob = blockIdx.y * 128;
    const int nb = blockIdx.x * 64;
    const int tid  = threadIdx.x;
    const int warp = tid >> 5;
    const int lane = tid & 31;
    const int g = lane >> 2, t = lane & 3;

    const float* gb = g_o + (size_t)b * HID * NPIX;

    float acc[2][8][4] = {};

    for (int kb = 0; kb < HID; kb += 16) {
        __syncthreads();
        #pragma unroll
        for (int j = 0; j < 4; j++) {
            int i = tid + j * 128;
            int o = i >> 2, k4 = (i & 3) * 4;
            float4 wv = *(const float4*)&w[(ob + o) * HID + kb + k4];
            unsigned h0, l0, h1, l1;
            split2_bf16(wv.x, wv.y, h0, l0);
            split2_bf16(wv.z, wv.w, h1, l1);
            *(uint2*)&Wh2[o * WST2 + k4 / 2] = make_uint2(h0, h1);
            *(uint2*)&Wl2[o * WST2 + k4 / 2] = make_uint2(l0, l1);
        }
        #pragma unroll
        for (int s = 0; s < 4; s++) {
            int i = tid + s * 128;
            int n = i & 63, k2 = i >> 6;
            const float* base = &gb[(size_t)(kb + 2 * k2) * NPIX + nb + n];
            unsigned h, l;
            split2_bf16(base[0], base[NPIX], h, l);
            Xh2[k2 * NST2 + n] = h;
            Xl2[k2 * NST2 + n] = l;
        }
        __syncthreads();

        unsigned ah[2][4], al[2][4];
        #pragma unroll
        for (int mf = 0; mf < 2; mf++) {
            const int wo = warp * 32 + mf * 16;
            ah[mf][0] = Wh2[(wo + g)     * WST2 + t];     al[mf][0] = Wl2[(wo + g)     * WST2 + t];
            ah[mf][1] = Wh2[(wo + 8 + g) * WST2 + t];     al[mf][1] = Wl2[(wo + 8 + g) * WST2 + t];
            ah[mf][2] = Wh2[(wo + g)     * WST2 + t + 4]; al[mf][2] = Wl2[(wo + g)     * WST2 + t + 4];
            ah[mf][3] = Wh2[(wo + 8 + g) * WST2 + t + 4]; al[mf][3] = Wl2[(wo + 8 + g) * WST2 + t + 4];
        }
        #pragma unroll
        for (int nt = 0; nt < 8; nt++) {
            unsigned b0h = Xh2[t       * NST2 + nt * 8 + g];
            unsigned b1h = Xh2[(t + 4) * NST2 + nt * 8 + g];
            unsigned b0l = Xl2[t       * NST2 + nt * 8 + g];
            unsigned b1l = Xl2[(t + 4) * NST2 + nt * 8 + g];
            mma_bf16(acc[0][nt], ah[0], b0h, b1h);
            mma_bf16(acc[0][nt], ah[0], b0l, b1l);
            mma_bf16(acc[0][nt], al[0], b0h, b1h);
            mma_bf16(acc[1][nt], ah[1], b0h, b1h);
            mma_bf16(acc[1][nt], ah[1], b0l, b1l);
            mma_bf16(acc[1][nt], al[1], b0h, b1h);
        }
    }

    #pragma unroll
    for (int mf = 0; mf < 2; mf++) {
        #pragma unroll
        for (int r = 0; r < 2; r++) {
            int o = ob + warp * 32 + mf * 16 + r * 8 + g;
            float bv = bias[o];
            float* row = out + (size_t)(b * CIN + o) * NPIX + nb + 2 * t;
            #pragma unroll
            for (int nt = 0; nt < 8; nt++)
                *(float2*)&row[nt * 8] = make_float2(acc[mf][nt][2 * r] + bv,
                                                     acc[mf][nt][2 * r + 1] + bv);
        }
    }
}

// ---------------------------------------------------------------------------
extern "C" void kernel_launch(void* const* d_in, const int* in_sizes, int n_in,
                              void* d_out, int out_size)
{
    const float* x     = (const float*)d_in[0];  // [8,256,48,48]
    const float* w_qkv = (const float*)d_in[1];  // [384,256]
    const float* w_out = (const float*)d_in[2];  // [256,128]
    const float* b_out = (const float*)d_in[3];  // [256]
    float* out = (float*)d_out;                  // [8,256,48,48]

    {
        dim3 grid(NPIX / 64, (3 * HID) / 128, BATCH);  // 36 x 3 x 8
        qkv_mma_kernel<<<grid, 128>>>(x, w_qkv);
    }
    {
        dim3 grid(NPIX / QTILE, BATCH * NHEADS);        // 18 x 32
        attn_mma_kernel<<<grid, 128>>>();
    }
    {
        dim3 grid(NPIX / 64, CIN / 128, BATCH);         // 36 x 2 x 8
        proj_mma_kernel<<<grid, 128>>>(w_out, b_out, out);
    }
}